// round 12
// baseline (speedup 1.0000x reference)
#include <cuda_runtime.h>

// Problem constants
#define YY 5
#define NN 200000
#define GG 128
#define II 128
#define RR 3
#define BB 1024
#define KK 64
#define KTOT (RR * GG)   // 384

#define NWEFF_BLK 192    // weff-builder CTAs prepended to gather grid
#define NSPLIT 4         // GEMM K-split factor
#define MTOT (YY * BB)   // 5120

// Scratch (no cudaMalloc allowed)
__device__ __align__(16) float g_mean[(size_t)MTOT * KTOT];        // [m][k]
__device__ __align__(16) float g_weff[KTOT * II];                  // [k][i]
__device__ __align__(16) float g_part[NSPLIT][(size_t)MTOT * II];  // partials

// ---------------------------------------------------------------------------
// Fused kernel #1 (1D grid, 128 threads)  — EXACT R8 gather (measured 41.1us):
//   blocks [0, 192):         build g_weff
//   blocks [192, 192+15360): gather + masked mean, one CTA per (y, r, b)
// ---------------------------------------------------------------------------
__global__ void __launch_bounds__(128) gather_mean_kernel(
        const float* __restrict__ emb,
        const void* __restrict__ nbr,
        const void* __restrict__ cnt,
        const float* __restrict__ Wrel,
        const float* __restrict__ Wcite) {
    const int bid = blockIdx.x;
    const int tid = threadIdx.x;

    if (bid < NWEFF_BLK) {
        #pragma unroll
        for (int j = 0; j < 2; ++j) {
            int idx = bid * 256 + j * 128 + tid;   // < 49152
            int r  = idx / (GG * II);
            int gi = idx - r * (GG * II);
            float v;
            if (r == 0)
                v = Wcite[gi] + Wcite[GG * II + gi] + Wcite[2 * GG * II + gi];
            else
                v = Wrel[idx];
            g_weff[idx] = v;
        }
        return;
    }

    const int gid = bid - NWEFF_BLK;
    const int y   = gid / (RR * BB);
    const int rem = gid - y * (RR * BB);
    const int r   = rem >> 10;
    const int b   = rem & (BB - 1);
    const int w    = tid >> 5;
    const int lane = tid & 31;

    __shared__ int   s_is64;
    __shared__ int   s_cnt;
    __shared__ __align__(16) int   sidx[KK];
    __shared__ __align__(16) float part[4][GG];

    // dtype detection (warp 0): odd words of first 32 int64 candidates
    if (w == 0) {
        unsigned int v = ((const unsigned int*)cnt)[2 * lane + 1];
        unsigned int m = __ballot_sync(0xffffffffu, v != 0u);
        if (lane == 0) s_is64 = (m == 0u) ? 1 : 0;
    }
    __syncthreads();
    const int is64 = s_is64;

    const long long lin = ((long long)y * RR + r) * BB + b;
    if (tid == 0) {
        s_cnt = is64 ? (int)((const long long*)cnt)[lin]
                     : ((const int*)cnt)[lin];
    }
    if (tid < KK) {
        sidx[tid] = is64 ? (int)((const long long*)nbr)[lin * KK + tid]
                         : ((const int*)nbr)[lin * KK + tid];
    }
    __syncthreads();
    const int count = s_cnt;

    // float4 view of this year's embedding slab; row stride = 32 float4s
    const float4* e = (const float4*)(emb + (size_t)y * NN * GG) + lane;

    float4 acc = make_float4(0.f, 0.f, 0.f, 0.f);
    int k = w;
    for (; k + 4 < count; k += 8) {
        float4 v0 = e[(size_t)sidx[k] * 32];
        float4 v1 = e[(size_t)sidx[k + 4] * 32];
        acc.x += v0.x + v1.x;
        acc.y += v0.y + v1.y;
        acc.z += v0.z + v1.z;
        acc.w += v0.w + v1.w;
    }
    if (k < count) {
        float4 v0 = e[(size_t)sidx[k] * 32];
        acc.x += v0.x; acc.y += v0.y; acc.z += v0.z; acc.w += v0.w;
    }

    *(float4*)&part[w][lane * 4] = acc;
    __syncthreads();

    const float inv = 1.0f / (float)(count > 0 ? count : 1);
    float s = part[0][tid] + part[1][tid] + part[2][tid] + part[3][tid];
    g_mean[((size_t)y * BB + b) * KTOT + r * GG + tid] = s * inv;
}

// ---------------------------------------------------------------------------
// K-split SGEMM partials, high-occupancy shape:
//   g_part[s][:, ct*64:+64] += A[:, s*96:+96] @ W[s*96:+96, ct*64:+64]
// Tile BM=32 x BN=64, BK=32, 3 chunks; 128 threads (4 warps);
// grid = 160 rowtiles x 2 coltiles x 4 ksplits = 1280 CTAs (~8 CTAs/SM).
// Warp w: rows w*8..w*8+7 (A via broadcast LDS.128); lane: 2 cols lane*2.
// 8 f32x2 accs/thread (16 regs). cp.async W; double-buffered; lb(128,8).
// ---------------------------------------------------------------------------
#define BM 32
#define BN 64
#define BK 32
#define KSPL (KTOT / NSPLIT)    // 96
#define NCHUNK (KSPL / BK)      // 3
#define APAD 8                  // A row stride 40 floats -> 16B-divisible

__device__ __forceinline__ unsigned long long fma2(unsigned long long a,
                                                   unsigned long long b,
                                                   unsigned long long c) {
    unsigned long long d;
    asm("fma.rn.f32x2 %0, %1, %2, %3;" : "=l"(d) : "l"(a), "l"(b), "l"(c));
    return d;
}
__device__ __forceinline__ unsigned long long dup2(float x) {
    unsigned long long d;
    unsigned int u = __float_as_uint(x);
    asm("mov.b64 %0, {%1, %1};" : "=l"(d) : "r"(u));
    return d;
}
__device__ __forceinline__ float2 unpk2(unsigned long long p) {
    unsigned int lo, hi;
    asm("mov.b64 {%0, %1}, %2;" : "=r"(lo), "=r"(hi) : "l"(p));
    return make_float2(__uint_as_float(lo), __uint_as_float(hi));
}
__device__ __forceinline__ void cp_async16(unsigned int smem_addr,
                                           const void* gptr) {
    asm volatile("cp.async.ca.shared.global [%0], [%1], 16;\n"
                 :: "r"(smem_addr), "l"(gptr));
}
__device__ __forceinline__ void cp_async_commit() {
    asm volatile("cp.async.commit_group;\n");
}
__device__ __forceinline__ void cp_async_wait0() {
    asm volatile("cp.async.wait_group 0;\n");
}

__global__ void __launch_bounds__(128, 8) gemm_partial_kernel() {
    __shared__ __align__(16) float Ast[2][BK][BM + APAD];  // transposed A
    __shared__ __align__(16) float Ws[2][BK][BN];

    const int tid  = threadIdx.x;        // 0..127
    const int w    = tid >> 5;           // warp 0..3 -> rows w*8..w*8+7
    const int lane = tid & 31;           // cols lane*2, lane*2+1
    const int ksplit  = blockIdx.x & (NSPLIT - 1);
    const int coltile = (blockIdx.x >> 2) & 1;
    const int rowbase = (blockIdx.x >> 3) * BM;
    const int colbase = coltile * BN;    // 0 or 64
    const int kbase   = ksplit * KSPL;

    unsigned long long acc[4][2];        // [rowpair][col]
    #pragma unroll
    for (int i = 0; i < 4; ++i) { acc[i][0] = 0ull; acc[i][1] = 0ull; }

    const float* Ag = g_mean + (size_t)rowbase * KTOT + kbase;
    const float* Wg = g_weff + (size_t)kbase * II + colbase;

    // staging maps
    const int wrow = tid >> 4;           // 0..7  (k within chunk, +8 per j)
    const int wcol = (tid & 15) << 2;    // 0..60

    unsigned int ws_base[2];
    ws_base[0] = (unsigned int)__cvta_generic_to_shared(&Ws[0][0][0]);
    ws_base[1] = (unsigned int)__cvta_generic_to_shared(&Ws[1][0][0]);

    // prologue: stage chunk 0 (A: 2 float4/thread; W: 4 cp.async/thread)
    {
        #pragma unroll
        for (int j = 0; j < 2; ++j) {
            int l = tid + j * 128;
            int rr = l >> 3, kc = (l & 7) << 2;
            float4 pa = *(const float4*)(Ag + (size_t)rr * KTOT + kc);
            Ast[0][kc + 0][rr] = pa.x;
            Ast[0][kc + 1][rr] = pa.y;
            Ast[0][kc + 2][rr] = pa.z;
            Ast[0][kc + 3][rr] = pa.w;
        }
        #pragma unroll
        for (int j = 0; j < 4; ++j) {
            int kr = wrow + j * 8;       // 0..31
            cp_async16(ws_base[0] + (unsigned int)((kr * BN + wcol) * 4),
                       Wg + (size_t)kr * II + wcol);
        }
        cp_async_commit();
        cp_async_wait0();
    }
    __syncthreads();

    for (int c = 0; c < NCHUNK; ++c) {
        const int buf = c & 1;
        const bool more = (c + 1 < NCHUNK);
        float4 pa0, pa1;
        if (more) {
            const int k0 = (c + 1) * BK;
            {
                int l = tid;
                pa0 = *(const float4*)(Ag + (size_t)(l >> 3) * KTOT + k0 + ((l & 7) << 2));
                l = tid + 128;
                pa1 = *(const float4*)(Ag + (size_t)(l >> 3) * KTOT + k0 + ((l & 7) << 2));
            }
            #pragma unroll
            for (int j = 0; j < 4; ++j) {
                int kr = wrow + j * 8;
                cp_async16(ws_base[buf ^ 1] + (unsigned int)((kr * BN + wcol) * 4),
                           Wg + (size_t)(k0 + kr) * II + wcol);
            }
            cp_async_commit();
        }

        #pragma unroll
        for (int kk = 0; kk < BK; ++kk) {
            ulonglong2 aP0 = *(const ulonglong2*)&Ast[buf][kk][w * 8];      // rows 0-3
            ulonglong2 aP1 = *(const ulonglong2*)&Ast[buf][kk][w * 8 + 4];  // rows 4-7
            float2 w2 = *(const float2*)&Ws[buf][kk][lane * 2];
            unsigned long long wd0 = dup2(w2.x), wd1 = dup2(w2.y);

            acc[0][0] = fma2(aP0.x, wd0, acc[0][0]);
            acc[0][1] = fma2(aP0.x, wd1, acc[0][1]);
            acc[1][0] = fma2(aP0.y, wd0, acc[1][0]);
            acc[1][1] = fma2(aP0.y, wd1, acc[1][1]);
            acc[2][0] = fma2(aP1.x, wd0, acc[2][0]);
            acc[2][1] = fma2(aP1.x, wd1, acc[2][1]);
            acc[3][0] = fma2(aP1.y, wd0, acc[3][0]);
            acc[3][1] = fma2(aP1.y, wd1, acc[3][1]);
        }

        if (more) {
            const int nbuf = buf ^ 1;
            {
                int l = tid;
                int rr = l >> 3, kc = (l & 7) << 2;
                Ast[nbuf][kc + 0][rr] = pa0.x;
                Ast[nbuf][kc + 1][rr] = pa0.y;
                Ast[nbuf][kc + 2][rr] = pa0.z;
                Ast[nbuf][kc + 3][rr] = pa0.w;
                l = tid + 128;
                rr = l >> 3; kc = (l & 7) << 2;
                Ast[nbuf][kc + 0][rr] = pa1.x;
                Ast[nbuf][kc + 1][rr] = pa1.y;
                Ast[nbuf][kc + 2][rr] = pa1.z;
                Ast[nbuf][kc + 3][rr] = pa1.w;
            }
            cp_async_wait0();
            __syncthreads();
        }
    }

    // epilogue: unpack row pairs, float2 per row into partial buffer
    float* p = g_part[ksplit] + (size_t)(rowbase + w * 8) * II + colbase + lane * 2;
    #pragma unroll
    for (int rp = 0; rp < 4; ++rp) {
        float2 c0 = unpk2(acc[rp][0]);   // col 0, rows (2rp, 2rp+1)
        float2 c1 = unpk2(acc[rp][1]);   // col 1
        *(float2*)(p + (size_t)(2 * rp) * II)     = make_float2(c0.x, c1.x);
        *(float2*)(p + (size_t)(2 * rp + 1) * II) = make_float2(c0.y, c1.y);
    }
}

// ---------------------------------------------------------------------------
// Reduce: out = p0 + p1 + p2 + p3. One float4 per thread (grid 640 x 256).
// ---------------------------------------------------------------------------
__global__ void __launch_bounds__(256) reduce_kernel(float* __restrict__ out) {
    const int idx = blockIdx.x * 256 + threadIdx.x;   // float4 index
    const float4* p0 = (const float4*)g_part[0];
    const float4* p1 = (const float4*)g_part[1];
    const float4* p2 = (const float4*)g_part[2];
    const float4* p3 = (const float4*)g_part[3];
    float4 a = p0[idx], b = p1[idx], c = p2[idx], d = p3[idx];
    float4 r;
    r.x = (a.x + b.x) + (c.x + d.x);
    r.y = (a.y + b.y) + (c.y + d.y);
    r.z = (a.z + b.z) + (c.z + d.z);
    r.w = (a.w + b.w) + (c.w + d.w);
    ((float4*)out)[idx] = r;
}

// ---------------------------------------------------------------------------
// kernel_launch: [weff-build + gather] -> K-split GEMM -> reduce
// ---------------------------------------------------------------------------
extern "C" void kernel_launch(void* const* d_in, const int* in_sizes, int n_in,
                              void* d_out, int out_size) {
    const float* emb   = (const float*)d_in[0];
    const float* Wrel  = (const float*)d_in[1];
    const float* Wcite = (const float*)d_in[2];
    const void*  nbr   = d_in[3];
    const void*  cnt   = d_in[4];
    float* out = (float*)d_out;

    gather_mean_kernel<<<NWEFF_BLK + YY * RR * BB, 128>>>(emb, nbr, cnt, Wrel, Wcite);

    gemm_partial_kernel<<<(MTOT / BM) * 2 * NSPLIT, 128>>>();

    reduce_kernel<<<(MTOT * II) / (256 * 4), 256>>>(out);
}

// round 13
// speedup vs baseline: 1.0538x; 1.0538x over previous
#include <cuda_runtime.h>

// Problem constants
#define YY 5
#define NN 200000
#define GG 128
#define II 128
#define RR 3
#define BB 1024
#define KK 64
#define KTOT (RR * GG)   // 384

#define NSPLIT 4         // GEMM K-split factor
#define MTOT (YY * BB)   // 5120
#define NGATHER (YY * RR * BB)   // 15360 gather CTAs (first in grid)
#define NWEFF_BLK 192            // weff-builder CTAs appended after gather

// Scratch (no cudaMalloc allowed)
__device__ __align__(16) float g_mean[(size_t)MTOT * KTOT];        // [m][k]
__device__ __align__(16) float g_weff[KTOT * II];                  // [k][i]
__device__ __align__(16) float g_part[NSPLIT][(size_t)MTOT * II];  // partials

// ---------------------------------------------------------------------------
// cp.async helpers
// ---------------------------------------------------------------------------
__device__ __forceinline__ void cp_async16_cg(unsigned int smem_addr,
                                              const void* gptr) {
    asm volatile("cp.async.cg.shared.global [%0], [%1], 16;\n"
                 :: "r"(smem_addr), "l"(gptr));
}
__device__ __forceinline__ void cp_async16(unsigned int smem_addr,
                                           const void* gptr) {
    asm volatile("cp.async.ca.shared.global [%0], [%1], 16;\n"
                 :: "r"(smem_addr), "l"(gptr));
}
__device__ __forceinline__ void cp_async_commit() {
    asm volatile("cp.async.commit_group;\n");
}
__device__ __forceinline__ void cp_async_wait0() {
    asm volatile("cp.async.wait_group 0;\n");
}
__device__ __forceinline__ void cp_async_wait2() {
    asm volatile("cp.async.wait_group 2;\n");
}

// ---------------------------------------------------------------------------
// Fused kernel #1 (1D grid, 128 threads):
//   blocks [0, 15360):        gather + masked mean, one CTA per (y, r, b)
//   blocks [15360, +192):     build g_weff
// Gather pipelines neighbor rows through a 4-deep smem ring with cp.async:
//   stage = 8 rows x 512B = 4KB; lookahead 3 stages in flight (12KB/CTA).
//   Every iteration commits a group (possibly empty) so group s == stage s
//   and wait_group 2 always retires stage s exactly.
// Consume: thread tid accumulates column tid over all staged rows -> no
// cross-warp reduction. int64/int32 detection per-CTA as before.
// ---------------------------------------------------------------------------
__global__ void __launch_bounds__(128) gather_mean_kernel(
        const float* __restrict__ emb,
        const void* __restrict__ nbr,
        const void* __restrict__ cnt,
        const float* __restrict__ Wrel,
        const float* __restrict__ Wcite) {
    const int bid = blockIdx.x;
    const int tid = threadIdx.x;

    if (bid >= NGATHER) {
        const int wb = bid - NGATHER;
        #pragma unroll
        for (int j = 0; j < 2; ++j) {
            int idx = wb * 256 + j * 128 + tid;   // < 49152
            int r  = idx / (GG * II);
            int gi = idx - r * (GG * II);
            float v;
            if (r == 0)
                v = Wcite[gi] + Wcite[GG * II + gi] + Wcite[2 * GG * II + gi];
            else
                v = Wrel[idx];
            g_weff[idx] = v;
        }
        return;
    }

    const int y   = bid / (RR * BB);
    const int rem = bid - y * (RR * BB);
    const int r   = rem >> 10;
    const int b   = rem & (BB - 1);
    const int w    = tid >> 5;
    const int lane = tid & 31;

    __shared__ int   s_is64;
    __shared__ int   s_cnt;
    __shared__ __align__(16) int   sidx[KK];
    __shared__ __align__(16) float SBUF[4][8][GG];   // 16 KB ring

    // dtype detection (warp 0): odd words of first 32 int64 candidates
    if (w == 0) {
        unsigned int v = ((const unsigned int*)cnt)[2 * lane + 1];
        unsigned int m = __ballot_sync(0xffffffffu, v != 0u);
        if (lane == 0) s_is64 = (m == 0u) ? 1 : 0;
    }
    __syncthreads();
    const int is64 = s_is64;

    const long long lin = ((long long)y * RR + r) * BB + b;
    if (tid == 0) {
        s_cnt = is64 ? (int)((const long long*)cnt)[lin]
                     : ((const int*)cnt)[lin];
    }
    if (tid < KK) {
        sidx[tid] = is64 ? (int)((const long long*)nbr)[lin * KK + tid]
                         : ((const int*)nbr)[lin * KK + tid];
    }
    __syncthreads();
    const int count = s_cnt;
    const int nst = (count + 7) >> 3;    // stages of 8 rows

    const char* ey = (const char*)(emb + (size_t)y * NN * GG);
    const unsigned int sb = (unsigned int)__cvta_generic_to_shared(&SBUF[0][0][0]);

    // chunk mapping for staging: thread handles chunks tid and tid+128
    // chunk c: row j = c>>5, byte offset (c&31)*16 within the row.
    const int j0 = tid >> 5,          off0 = (tid & 31) << 4;
    const int j1 = (tid + 128) >> 5,  off1 = (tid & 31) << 4;   // j1 = j0+4

    // prologue: issue stages 0..2 (empty commits keep group<->stage 1:1)
    #pragma unroll
    for (int p = 0; p < 3; ++p) {
        if (p < nst) {
            const int base = p * 8;
            const unsigned int d = sb + (unsigned int)((p & 3) * 4096);
            if (base + j0 < count)
                cp_async16_cg(d + (unsigned int)(j0 * 512 + off0),
                              ey + ((size_t)sidx[base + j0] << 9) + off0);
            if (base + j1 < count)
                cp_async16_cg(d + (unsigned int)(j1 * 512 + off1),
                              ey + ((size_t)sidx[base + j1] << 9) + off1);
        }
        cp_async_commit();
    }

    float acc = 0.0f;
    for (int s = 0; s < nst; ++s) {
        cp_async_wait2();      // stage s complete (pending <= 2 newer groups)
        __syncthreads();       // staged data visible to all threads

        // issue stage s+3 into ring slot (s+3)&3 (consumed at iter s-1)
        if (s + 3 < nst) {
            const int base = (s + 3) * 8;
            const unsigned int d = sb + (unsigned int)(((s + 3) & 3) * 4096);
            if (base + j0 < count)
                cp_async16_cg(d + (unsigned int)(j0 * 512 + off0),
                              ey + ((size_t)sidx[base + j0] << 9) + off0);
            if (base + j1 < count)
                cp_async16_cg(d + (unsigned int)(j1 * 512 + off1),
                              ey + ((size_t)sidx[base + j1] << 9) + off1);
        }
        cp_async_commit();

        // consume stage s: thread tid owns column tid of each row
        const int buf = s & 3;
        const int rm  = count - s * 8;
        if (rm >= 8) {
            float t0 = SBUF[buf][0][tid] + SBUF[buf][1][tid];
            float t1 = SBUF[buf][2][tid] + SBUF[buf][3][tid];
            float t2 = SBUF[buf][4][tid] + SBUF[buf][5][tid];
            float t3 = SBUF[buf][6][tid] + SBUF[buf][7][tid];
            acc += (t0 + t1) + (t2 + t3);
        } else {
            for (int j = 0; j < rm; ++j)
                acc += SBUF[buf][j][tid];
        }
    }
    cp_async_wait0();          // drain before CTA exit

    const float inv = 1.0f / (float)(count > 0 ? count : 1);
    g_mean[((size_t)y * BB + b) * KTOT + r * GG + tid] = acc * inv;
}

// ---------------------------------------------------------------------------
// K-split SGEMM partials (EXACT R8 shape — best measured):
//   g_part[s] = A[:, s*96:(s+1)*96] @ W[s*96:(s+1)*96, :]
// Tile BM=32 x BN=128, BK=32, 3 chunks; 128 threads; grid = 160 x 4 = 640.
// Warp w: rows w*8..w*8+7; lane: cols lane*4..+3 -> 16 f32x2 accs/thread.
// ---------------------------------------------------------------------------
#define BM 32
#define BN 128
#define BK 32
#define KSPL (KTOT / NSPLIT)    // 96
#define NCHUNK (KSPL / BK)      // 3
#define APAD 8

__device__ __forceinline__ unsigned long long fma2(unsigned long long a,
                                                   unsigned long long b,
                                                   unsigned long long c) {
    unsigned long long d;
    asm("fma.rn.f32x2 %0, %1, %2, %3;" : "=l"(d) : "l"(a), "l"(b), "l"(c));
    return d;
}
__device__ __forceinline__ unsigned long long dup2(float x) {
    unsigned long long d;
    unsigned int u = __float_as_uint(x);
    asm("mov.b64 %0, {%1, %1};" : "=l"(d) : "r"(u));
    return d;
}
__device__ __forceinline__ float2 unpk2(unsigned long long p) {
    unsigned int lo, hi;
    asm("mov.b64 {%0, %1}, %2;" : "=r"(lo), "=r"(hi) : "l"(p));
    return make_float2(__uint_as_float(lo), __uint_as_float(hi));
}

__global__ void __launch_bounds__(128) gemm_partial_kernel() {
    __shared__ __align__(16) float Ast[2][BK][BM + APAD];  // transposed A
    __shared__ __align__(16) float Ws[2][BK][BN];

    const int tid  = threadIdx.x;        // 0..127
    const int w    = tid >> 5;           // warp 0..3 -> rows w*8..w*8+7
    const int lane = tid & 31;           // cols lane*4..lane*4+3
    const int ksplit  = blockIdx.x & (NSPLIT - 1);
    const int rowbase = (blockIdx.x >> 2) * BM;
    const int kbase   = ksplit * KSPL;

    unsigned long long acc[4][4];        // [rowpair][col]
    #pragma unroll
    for (int i = 0; i < 4; ++i)
        #pragma unroll
        for (int j = 0; j < 4; ++j) acc[i][j] = 0ull;

    const float* Ag = g_mean + (size_t)rowbase * KTOT + kbase;
    const float* Wg = g_weff + (size_t)kbase * BN;

    const int wrow = tid >> 5;           // 0..3   (k within chunk, +4 per j)
    const int wcol = (tid & 31) << 2;    // 0..124

    unsigned int ws_base[2];
    ws_base[0] = (unsigned int)__cvta_generic_to_shared(&Ws[0][0][0]);
    ws_base[1] = (unsigned int)__cvta_generic_to_shared(&Ws[1][0][0]);

    // prologue: stage chunk 0 (A: 2 float4/thread; W: 8 cp.async/thread)
    {
        #pragma unroll
        for (int j = 0; j < 2; ++j) {
            int l = tid + j * 128;
            int rr = l >> 3, kc = (l & 7) << 2;
            float4 pa = *(const float4*)(Ag + (size_t)rr * KTOT + kc);
            Ast[0][kc + 0][rr] = pa.x;
            Ast[0][kc + 1][rr] = pa.y;
            Ast[0][kc + 2][rr] = pa.z;
            Ast[0][kc + 3][rr] = pa.w;
        }
        #pragma unroll
        for (int j = 0; j < 8; ++j) {
            int kr = wrow + j * 4;       // 0..31
            cp_async16(ws_base[0] + (unsigned int)((kr * BN + wcol) * 4),
                       Wg + (size_t)kr * BN + wcol);
        }
        cp_async_commit();
        cp_async_wait0();
    }
    __syncthreads();

    for (int c = 0; c < NCHUNK; ++c) {
        const int buf = c & 1;
        const bool more = (c + 1 < NCHUNK);
        float4 pa0, pa1;
        if (more) {
            const int k0 = (c + 1) * BK;
            {
                int l = tid;
                pa0 = *(const float4*)(Ag + (size_t)(l >> 3) * KTOT + k0 + ((l & 7) << 2));
                l = tid + 128;
                pa1 = *(const float4*)(Ag + (size_t)(l >> 3) * KTOT + k0 + ((l & 7) << 2));
            }
            #pragma unroll
            for (int j = 0; j < 8; ++j) {
                int kr = wrow + j * 4;
                cp_async16(ws_base[buf ^ 1] + (unsigned int)((kr * BN + wcol) * 4),
                           Wg + (size_t)(k0 + kr) * BN + wcol);
            }
            cp_async_commit();
        }

        #pragma unroll
        for (int kk = 0; kk < BK; ++kk) {
            ulonglong2 aP0 = *(const ulonglong2*)&Ast[buf][kk][w * 8];      // rows 0-3
            ulonglong2 aP1 = *(const ulonglong2*)&Ast[buf][kk][w * 8 + 4];  // rows 4-7
            float4 w4 = *(const float4*)&Ws[buf][kk][lane * 4];
            unsigned long long wd0 = dup2(w4.x), wd1 = dup2(w4.y);
            unsigned long long wd2 = dup2(w4.z), wd3 = dup2(w4.w);

            acc[0][0] = fma2(aP0.x, wd0, acc[0][0]);
            acc[0][1] = fma2(aP0.x, wd1, acc[0][1]);
            acc[0][2] = fma2(aP0.x, wd2, acc[0][2]);
            acc[0][3] = fma2(aP0.x, wd3, acc[0][3]);
            acc[1][0] = fma2(aP0.y, wd0, acc[1][0]);
            acc[1][1] = fma2(aP0.y, wd1, acc[1][1]);
            acc[1][2] = fma2(aP0.y, wd2, acc[1][2]);
            acc[1][3] = fma2(aP0.y, wd3, acc[1][3]);
            acc[2][0] = fma2(aP1.x, wd0, acc[2][0]);
            acc[2][1] = fma2(aP1.x, wd1, acc[2][1]);
            acc[2][2] = fma2(aP1.x, wd2, acc[2][2]);
            acc[2][3] = fma2(aP1.x, wd3, acc[2][3]);
            acc[3][0] = fma2(aP1.y, wd0, acc[3][0]);
            acc[3][1] = fma2(aP1.y, wd1, acc[3][1]);
            acc[3][2] = fma2(aP1.y, wd2, acc[3][2]);
            acc[3][3] = fma2(aP1.y, wd3, acc[3][3]);
        }

        if (more) {
            const int nbuf = buf ^ 1;
            {
                int l = tid;
                int rr = l >> 3, kc = (l & 7) << 2;
                Ast[nbuf][kc + 0][rr] = pa0.x;
                Ast[nbuf][kc + 1][rr] = pa0.y;
                Ast[nbuf][kc + 2][rr] = pa0.z;
                Ast[nbuf][kc + 3][rr] = pa0.w;
                l = tid + 128;
                rr = l >> 3; kc = (l & 7) << 2;
                Ast[nbuf][kc + 0][rr] = pa1.x;
                Ast[nbuf][kc + 1][rr] = pa1.y;
                Ast[nbuf][kc + 2][rr] = pa1.z;
                Ast[nbuf][kc + 3][rr] = pa1.w;
            }
            cp_async_wait0();
            __syncthreads();
        }
    }

    // epilogue: unpack row pairs, float4 per row into partial buffer
    float* p = g_part[ksplit] + (size_t)(rowbase + w * 8) * BN + lane * 4;
    #pragma unroll
    for (int rp = 0; rp < 4; ++rp) {
        float2 c0 = unpk2(acc[rp][0]);
        float2 c1 = unpk2(acc[rp][1]);
        float2 c2 = unpk2(acc[rp][2]);
        float2 c3 = unpk2(acc[rp][3]);
        *(float4*)(p + (size_t)(2 * rp) * BN)     = make_float4(c0.x, c1.x, c2.x, c3.x);
        *(float4*)(p + (size_t)(2 * rp + 1) * BN) = make_float4(c0.y, c1.y, c2.y, c3.y);
    }
}

// ---------------------------------------------------------------------------
// Reduce: out = p0 + p1 + p2 + p3. One float4 per thread (grid 640 x 256).
// ---------------------------------------------------------------------------
__global__ void __launch_bounds__(256) reduce_kernel(float* __restrict__ out) {
    const int idx = blockIdx.x * 256 + threadIdx.x;   // float4 index
    const float4* p0 = (const float4*)g_part[0];
    const float4* p1 = (const float4*)g_part[1];
    const float4* p2 = (const float4*)g_part[2];
    const float4* p3 = (const float4*)g_part[3];
    float4 a = p0[idx], b = p1[idx], c = p2[idx], d = p3[idx];
    float4 r;
    r.x = (a.x + b.x) + (c.x + d.x);
    r.y = (a.y + b.y) + (c.y + d.y);
    r.z = (a.z + b.z) + (c.z + d.z);
    r.w = (a.w + b.w) + (c.w + d.w);
    ((float4*)out)[idx] = r;
}

// ---------------------------------------------------------------------------
// kernel_launch: [gather + weff-build] -> K-split GEMM -> reduce
// ---------------------------------------------------------------------------
extern "C" void kernel_launch(void* const* d_in, const int* in_sizes, int n_in,
                              void* d_out, int out_size) {
    const float* emb   = (const float*)d_in[0];
    const float* Wrel  = (const float*)d_in[1];
    const float* Wcite = (const float*)d_in[2];
    const void*  nbr   = d_in[3];
    const void*  cnt   = d_in[4];
    float* out = (float*)d_out;

    gather_mean_kernel<<<NGATHER + NWEFF_BLK, 128>>>(emb, nbr, cnt, Wrel, Wcite);

    gemm_partial_kernel<<<(MTOT / BM) * NSPLIT, 128>>>();

    reduce_kernel<<<(MTOT * II) / (256 * 4), 256>>>(out);
}